// round 10
// baseline (speedup 1.0000x reference)
#include <cuda_runtime.h>
#include <cuda_bf16.h>
#include <math.h>
#include <stdint.h>

#define B_  2
#define L_  2048
#define H_  1024
#define NH_ 16
#define HD_ 64
#define BH_ 32
#define M_  4096
#define MAXPOS_ 2048
#define NDIST 4095

// ---------------- device-global scratch (allocation-free) ----------------
__device__ __nv_bfloat16 g_hhi[(size_t)M_*H_];
__device__ __nv_bfloat16 g_hlo[(size_t)M_*H_];
__device__ __nv_bfloat16 g_whi[3][(size_t)H_*H_];
__device__ __nv_bfloat16 g_wlo[3][(size_t)H_*H_];
__device__ __nv_bfloat16 g_qhi[(size_t)BH_*L_*HD_];
__device__ __nv_bfloat16 g_qlo[(size_t)BH_*L_*HD_];
__device__ __nv_bfloat16 g_khi[(size_t)BH_*L_*HD_];
__device__ __nv_bfloat16 g_klo[(size_t)BH_*L_*HD_];
__device__ __nv_bfloat16 g_vhi[(size_t)BH_*L_*HD_];
__device__ __nv_bfloat16 g_vlo[(size_t)BH_*L_*HD_];
__device__ __nv_bfloat16 g_e[(size_t)NDIST*HD_];

// ---------------- helpers ----------------
__device__ __forceinline__ uint32_t smem_u32(const void* p){
    return (uint32_t)__cvta_generic_to_shared(p);
}
__device__ __forceinline__ void ldsm4(uint32_t* r, uint32_t a){
    asm volatile("ldmatrix.sync.aligned.m8n8.x4.shared.b16 {%0,%1,%2,%3}, [%4];"
        : "=r"(r[0]),"=r"(r[1]),"=r"(r[2]),"=r"(r[3]) : "r"(a));
}
__device__ __forceinline__ void ldsm4t(uint32_t* r, uint32_t a){
    asm volatile("ldmatrix.sync.aligned.m8n8.x4.trans.shared.b16 {%0,%1,%2,%3}, [%4];"
        : "=r"(r[0]),"=r"(r[1]),"=r"(r[2]),"=r"(r[3]) : "r"(a));
}
__device__ __forceinline__ void mma_bf16(float* c, const uint32_t* a, uint32_t b0, uint32_t b1){
    asm volatile(
        "mma.sync.aligned.m16n8k16.row.col.f32.bf16.bf16.f32 "
        "{%0,%1,%2,%3},{%4,%5,%6,%7},{%8,%9},{%0,%1,%2,%3};"
        : "+f"(c[0]), "+f"(c[1]), "+f"(c[2]), "+f"(c[3])
        : "r"(a[0]), "r"(a[1]), "r"(a[2]), "r"(a[3]), "r"(b0), "r"(b1));
}
__device__ __forceinline__ uint32_t packbf(float x, float y){
    __nv_bfloat162 h = __floats2bfloat162_rn(x, y);
    return *reinterpret_cast<uint32_t*>(&h);
}
__device__ __forceinline__ void cp16(uint32_t dst, const void* src){
    asm volatile("cp.async.cg.shared.global [%0], [%1], 16;" :: "r"(dst), "l"(src));
}
__device__ __forceinline__ void cp_commit(){
    asm volatile("cp.async.commit_group;" ::: "memory");
}
template<int N>
__device__ __forceinline__ void cp_wait(){
    asm volatile("cp.async.wait_group %0;" :: "n"(N) : "memory");
}
// tiles with 128B rows (64 bf16); chunk = 16B unit, xor-swizzled
__device__ __forceinline__ uint32_t sw_addr(char* sm, int off, int row, int ch){
    return smem_u32(sm + off + row*128 + (((ch) ^ (row & 7)) << 4));
}

// ---------------- prep: fp32 -> bf16 hi/lo planes ----------------
__global__ void prep_split(const float* __restrict__ s, int which, int n){
    int i = blockIdx.x*256 + threadIdx.x;
    if (i >= n) return;
    __nv_bfloat16 *hi, *lo;
    if (which==0){hi=g_hhi; lo=g_hlo;}
    else if (which==1){hi=g_whi[0]; lo=g_wlo[0];}
    else if (which==2){hi=g_whi[1]; lo=g_wlo[1];}
    else {hi=g_whi[2]; lo=g_wlo[2];}
    float x = s[i];
    __nv_bfloat16 h = __float2bfloat16(x);
    hi[i] = h;
    lo[i] = __float2bfloat16(x - __bfloat162float(h));
}
__global__ void prep_e_kernel(const float* __restrict__ s){
    int i = blockIdx.x*256 + threadIdx.x;
    if (i < NDIST*HD_) g_e[i] = __float2bfloat16(s[i]);
}

// ---------------- QKV projection: split-bf16 mma, double-buffered ----------
#define QA_HI 0
#define QA_LO 16384
#define QB_HI 32768
#define QB_LO 40960
#define QKV_STAGE 49152
#define QKV_SMEM (2*QKV_STAGE)

__global__ __launch_bounds__(128) void qkv_mma(
    const float* __restrict__ bq, const float* __restrict__ bk,
    const float* __restrict__ bv)
{
    extern __shared__ char sm[];
    const int which = blockIdx.z;
    const __nv_bfloat16* Whi = g_whi[which];
    const __nv_bfloat16* Wlo = g_wlo[which];
    const float* bias = (which==0) ? bq : (which==1) ? bk : bv;
    __nv_bfloat16* Ohi = (which==0) ? g_qhi : (which==1) ? g_khi : g_vhi;
    __nv_bfloat16* Olo = (which==0) ? g_qlo : (which==1) ? g_klo : g_vlo;

    const int m0 = blockIdx.y * 128;
    const int n0 = blockIdx.x * 64;
    const int t  = threadIdx.x;
    const int w  = t >> 5;
    const int lane = t & 31;
    const int quad = lane & 3;
    const int g8  = lane >> 3;
    const int il7 = lane & 7;

    float c[2][8][4];
#pragma unroll
    for (int s = 0; s < 2; s++)
#pragma unroll
        for (int n = 0; n < 8; n++)
#pragma unroll
            for (int j = 0; j < 4; j++) c[s][n][j] = 0.f;

#define QKV_ISSUE(buf, k0) do {                                               \
        int base = (buf)*QKV_STAGE;                                           \
        _Pragma("unroll")                                                     \
        for (int rep = 0; rep < 2; rep++){                                    \
            int id = t + 128*rep;                                             \
            int plane = id >> 7, row = id & 127;                              \
            const char* gs = (const char*)((plane ? g_hlo : g_hhi)            \
                + (size_t)(m0+row)*H_ + (k0));                                \
            int off = base + (plane ? QA_LO : QA_HI);                         \
            _Pragma("unroll")                                                 \
            for (int cc = 0; cc < 8; cc++)                                    \
                cp16(sw_addr(sm, off, row, cc), gs + cc*16);                  \
        }                                                                     \
        {                                                                     \
            int plane = t >> 6, row = t & 63;                                 \
            const char* gs = (const char*)((plane ? Wlo : Whi)                \
                + (size_t)(n0+row)*H_ + (k0));                                \
            int off = base + (plane ? QB_LO : QB_HI);                         \
            _Pragma("unroll")                                                 \
            for (int cc = 0; cc < 8; cc++)                                    \
                cp16(sw_addr(sm, off, row, cc), gs + cc*16);                  \
        }                                                                     \
        cp_commit();                                                          \
    } while(0)

    QKV_ISSUE(0, 0);

    for (int ki = 0; ki < 16; ki++){
        if (ki < 15) QKV_ISSUE((ki+1)&1, (ki+1)*64);
        if (ki < 15) cp_wait<1>(); else cp_wait<0>();
        __syncthreads();
        int base = (ki&1)*QKV_STAGE;

#pragma unroll
        for (int kk = 0; kk < 4; kk++){
            uint32_t ah[2][4], al[2][4];
#pragma unroll
            for (int s = 0; s < 2; s++){
                int row = 32*w + 16*s + (lane & 15);
                int ch  = 2*kk + (lane >> 4);
                ldsm4(ah[s], sw_addr(sm, base+QA_HI, row, ch));
                ldsm4(al[s], sw_addr(sm, base+QA_LO, row, ch));
            }
#pragma unroll
            for (int n2 = 0; n2 < 4; n2++){
                int row = 8*(2*n2 + (g8>>1)) + il7;
                int ch  = 2*kk + (g8&1);
                uint32_t bh4[4], bl4[4];
                ldsm4(bh4, sw_addr(sm, base+QB_HI, row, ch));
                ldsm4(bl4, sw_addr(sm, base+QB_LO, row, ch));
#pragma unroll
                for (int s = 0; s < 2; s++){
                    mma_bf16(c[s][2*n2  ], ah[s], bh4[0], bh4[1]);
                    mma_bf16(c[s][2*n2  ], ah[s], bl4[0], bl4[1]);
                    mma_bf16(c[s][2*n2  ], al[s], bh4[0], bh4[1]);
                    mma_bf16(c[s][2*n2+1], ah[s], bh4[2], bh4[3]);
                    mma_bf16(c[s][2*n2+1], ah[s], bl4[2], bl4[3]);
                    mma_bf16(c[s][2*n2+1], al[s], bh4[2], bh4[3]);
                }
            }
        }
        __syncthreads();
    }

    const int h = n0 >> 6;
#pragma unroll
    for (int s = 0; s < 2; s++){
#pragma unroll
        for (int n = 0; n < 8; n++){
            int col = 8*n + 2*quad;
            float b0f = bias[n0+col], b1f = bias[n0+col+1];
#pragma unroll
            for (int half = 0; half < 2; half++){
                int mr = m0 + 32*w + 16*s + (lane>>2) + half*8;
                float f0 = c[s][n][half*2+0] + b0f;
                float f1 = c[s][n][half*2+1] + b1f;
                int b_ = mr >> 11, l = mr & (L_-1);
                size_t idx = (((size_t)(b_*NH_ + h))*L_ + l)*HD_ + col;
                __nv_bfloat16 h0 = __float2bfloat16(f0);
                __nv_bfloat16 h1 = __float2bfloat16(f1);
                __nv_bfloat162 hp = __halves2bfloat162(h0, h1);
                __nv_bfloat162 lp = __halves2bfloat162(
                    __float2bfloat16(f0 - __bfloat162float(h0)),
                    __float2bfloat16(f1 - __bfloat162float(h1)));
                *(uint32_t*)&Ohi[idx] = *(uint32_t*)&hp;
                *(uint32_t*)&Olo[idx] = *(uint32_t*)&lp;
            }
        }
    }
}

// ---------------- fused flash attention: pipelined mma mainloop ----------
// SMEM (bytes):
//   K/E stage s (s=0,1): KHI s*32768, KLO s*32768+8192, E s*32768+16384 (16384)
//   V hi/lo: 65536 / 73728   (single buffer, late-waited)
//   QE band 81920 (8704), KE band 90624 (8704)  [64][68] bf16
//   Q hi/lo aliased at 81920 / 90112 (dead after fragment load)
#define ST_KHI(s) ((s)*32768)
#define ST_KLO(s) ((s)*32768 + 8192)
#define ST_E(s)   ((s)*32768 + 16384)
#define F_VHI 65536
#define F_VLO 73728
#define F_QE  81920
#define F_KE  90624
#define F_QHI 81920
#define F_QLO 90112
#define FLASH_SMEM 99328

__global__ __launch_bounds__(128) void flash_kernel(
    const float* __restrict__ mask, float* __restrict__ out)
{
    extern __shared__ char sm[];
    const int bh = blockIdx.y;
    const int l0 = blockIdx.x * 64;
    const int t  = threadIdx.x;
    const int w  = t >> 5;
    const int lane = t & 31;
    const int quad = lane & 3;
    const int g8  = lane >> 3;
    const int il7 = lane & 7;
    const int lw = 16*w + (lane >> 2);
    const size_t gb = (size_t)bh * L_ * HD_;
    const int b_ = bh >> 4, head = bh & 15;
    const float* maskrow = mask + (size_t)b_ * L_;

    // ---- prologue: stage Q (group 1), then K/E[0] (group 2) ----
    {
        int plane = t >> 6, row = t & 63;
        const char* gs = (const char*)((plane ? g_qlo : g_qhi) + gb + (size_t)(l0+row)*HD_);
        int off = (plane ? F_QLO : F_QHI);
#pragma unroll
        for (int cc = 0; cc < 8; cc++)
            cp16(sw_addr(sm, off, row, cc), gs + cc*16);
    }
    cp_commit();
    {
        int tile = t >> 6, row = t & 63;
        const char* gk = (const char*)((tile ? g_klo : g_khi) + gb + (size_t)row*HD_);
        int off = tile ? ST_KLO(0) : ST_KHI(0);
#pragma unroll
        for (int cc = 0; cc < 8; cc++)
            cp16(sw_addr(sm, off, row, cc), gk + cc*16);
        int gbase = l0 + (MAXPOS_ - 1) - 63;
        if (t < 127){
            const char* ge = (const char*)(g_e + (size_t)(gbase + t)*HD_);
#pragma unroll
            for (int cc = 0; cc < 8; cc++)
                cp16(sw_addr(sm, ST_E(0), t, cc), ge + cc*16);
        } else {
            uint4 z = make_uint4(0,0,0,0);
            char* d = sm + ST_E(0) + 127*128;
#pragma unroll
            for (int cc = 0; cc < 8; cc++)
                *(uint4*)(d + ((cc ^ 7) << 4)) = z;
        }
    }
    cp_commit();
    cp_wait<1>();          // Q landed; K/E[0] still in flight
    __syncthreads();

    uint32_t qh[4][4], ql[4][4];
#pragma unroll
    for (int kk = 0; kk < 4; kk++){
        int row = 16*w + (lane & 15);
        int ch  = 2*kk + (lane >> 4);
        ldsm4(qh[kk], sw_addr(sm, F_QHI, row, ch));
        ldsm4(ql[kk], sw_addr(sm, F_QLO, row, ch));
    }

    float o[8][4];
#pragma unroll
    for (int n = 0; n < 8; n++)
#pragma unroll
        for (int j = 0; j < 4; j++) o[n][j] = 0.f;
    float m0r = -1e30f, m1r = -1e30f, ls0 = 0.f, ls1 = 0.f;

    for (int r0 = 0; r0 < L_; r0 += 64){
        const int s    = (r0 >> 6) & 1;
        const bool more = (r0 + 64 < L_);

        cp_wait<0>();      // K/E[i] landed (in flight since iter i-1)
        __syncthreads();   // visible to all; prev readers (PV/V, bands) done

        // issue V[i] -> single V buffer              (group: V)
        {
            int tile = t >> 6, row = t & 63;
            const char* gv = (const char*)((tile ? g_vlo : g_vhi) + gb + (size_t)(r0+row)*HD_);
            int off = tile ? F_VLO : F_VHI;
#pragma unroll
            for (int cc = 0; cc < 8; cc++)
                cp16(sw_addr(sm, off, row, cc), gv + cc*16);
        }
        cp_commit();
        // issue K/E[i+1] -> other stage              (group: KE-next)
        if (more){
            int sn = s ^ 1;
            int tile = t >> 6, row = t & 63;
            const char* gk = (const char*)((tile ? g_klo : g_khi) + gb + (size_t)(r0+64+row)*HD_);
            int off = tile ? ST_KLO(sn) : ST_KHI(sn);
#pragma unroll
            for (int cc = 0; cc < 8; cc++)
                cp16(sw_addr(sm, off, row, cc), gk + cc*16);
            int gbase = l0 - (r0+64) + (MAXPOS_ - 1) - 63;
            if (t < 127){
                const char* ge = (const char*)(g_e + (size_t)(gbase + t)*HD_);
#pragma unroll
                for (int cc = 0; cc < 8; cc++)
                    cp16(sw_addr(sm, ST_E(sn), t, cc), ge + cc*16);
            } else {
                uint4 z = make_uint4(0,0,0,0);
                char* d = sm + ST_E(sn) + 127*128;
#pragma unroll
                for (int cc = 0; cc < 8; cc++)
                    *(uint4*)(d + ((cc ^ 7) << 4)) = z;
            }
            cp_commit();
        }

        // ---- QE/KE bias GEMMs -> band-compact stages ----
        {
            uint32_t ka[4][4];
#pragma unroll
            for (int kk = 0; kk < 4; kk++){
                int row = 16*w + (lane & 15);
                int ch  = 2*kk + (lane >> 4);
                ldsm4(ka[kk], sw_addr(sm, ST_KHI(s), row, ch));
            }
            __nv_bfloat16* qe = (__nv_bfloat16*)(sm + F_QE);
            __nv_bfloat16* ke = (__nv_bfloat16*)(sm + F_KE);
            const int nq0 = 2*w;
            const int nk0 = 6 - 2*w;
#pragma unroll
            for (int p = 0; p < 5; p++){
                float cq[2][4] = {{0.f,0.f,0.f,0.f},{0.f,0.f,0.f,0.f}};
                float ck[2][4] = {{0.f,0.f,0.f,0.f},{0.f,0.f,0.f,0.f}};
#pragma unroll
                for (int kk = 0; kk < 4; kk++){
                    int ch = 2*kk + (g8&1);
                    uint32_t eq[4], ek[4];
                    ldsm4(eq, sw_addr(sm, ST_E(s), 8*(nq0 + 2*p + (g8>>1)) + il7, ch));
                    ldsm4(ek, sw_addr(sm, ST_E(s), 8*(nk0 + 2*p + (g8>>1)) + il7, ch));
                    mma_bf16(cq[0], qh[kk], eq[0], eq[1]);
                    mma_bf16(cq[1], qh[kk], eq[2], eq[3]);
                    mma_bf16(ck[0], ka[kk], ek[0], ek[1]);
                    mma_bf16(ck[1], ka[kk], ek[2], ek[3]);
                }
#pragma unroll
                for (int u = 0; u < 2; u++){
                    int cqc = 8*(nq0 + 2*p + u) + 2*quad;
                    int ckc = 8*(nk0 + 2*p + u) + 2*quad;
#pragma unroll
                    for (int j = 0; j < 2; j++){
                        int a0 = cqc + j - lw + 2;
                        if ((unsigned)a0 < 68u) qe[lw*68 + a0] = __float2bfloat16(cq[u][j]);
                        int a1 = cqc + j - (lw+8) + 2;
                        if ((unsigned)a1 < 68u) qe[(lw+8)*68 + a1] = __float2bfloat16(cq[u][j+2]);
                        int a2 = ckc + j + lw - 61;
                        if ((unsigned)a2 < 68u) ke[lw*68 + a2] = __float2bfloat16(ck[u][j]);
                        int a3 = ckc + j + (lw+8) - 61;
                        if ((unsigned)a3 < 68u) ke[(lw+8)*68 + a3] = __float2bfloat16(ck[u][j+2]);
                    }
                }
            }
        }
        __syncthreads();

        // ---- S1 = Q@K^T (3-mma split), C init from compact band gathers ----
        float sc[8][4];
        const __nv_bfloat16* qe = (const __nv_bfloat16*)(sm + F_QE);
        const __nv_bfloat16* ke = (const __nv_bfloat16*)(sm + F_KE);
#pragma unroll
        for (int n = 0; n < 8; n++){
            int rb = 8*n + 2*quad;
            sc[n][0] = __bfloat162float(qe[lw*68 + (65-rb)])
                     + __bfloat162float(ke[rb*68 + lw + 2]);
            sc[n][1] = __bfloat162float(qe[lw*68 + (64-rb)])
                     + __bfloat162float(ke[(rb+1)*68 + lw + 2]);
            sc[n][2] = __bfloat162float(qe[(lw+8)*68 + (65-rb)])
                     + __bfloat162float(ke[rb*68 + lw + 10]);
            sc[n][3] = __bfloat162float(qe[(lw+8)*68 + (64-rb)])
                     + __bfloat162float(ke[(rb+1)*68 + lw + 10]);
        }
#pragma unroll
        for (int n2 = 0; n2 < 4; n2++){
#pragma unroll
            for (int kk = 0; kk < 4; kk++){
                int row = 8*(2*n2 + (g8>>1)) + il7;
                int ch  = 2*kk + (g8&1);
                uint32_t kh4[4], kl4[4];
                ldsm4(kh4, sw_addr(sm, ST_KHI(s), row, ch));
                ldsm4(kl4, sw_addr(sm, ST_KLO(s), row, ch));
                mma_bf16(sc[2*n2  ], qh[kk], kh4[0], kh4[1]);
                mma_bf16(sc[2*n2  ], qh[kk], kl4[0], kl4[1]);
                mma_bf16(sc[2*n2  ], ql[kk], kh4[0], kh4[1]);
                mma_bf16(sc[2*n2+1], qh[kk], kh4[2], kh4[3]);
                mma_bf16(sc[2*n2+1], qh[kk], kl4[2], kl4[3]);
                mma_bf16(sc[2*n2+1], ql[kk], kh4[2], kh4[3]);
            }
        }

        // logits = sc*0.125 + mask (direct gmem, L2-hot)
#pragma unroll
        for (int n = 0; n < 8; n++){
            float2 mk = *(const float2*)&maskrow[r0 + 8*n + 2*quad];
            sc[n][0] = sc[n][0]*0.125f + mk.x;
            sc[n][1] = sc[n][1]*0.125f + mk.y;
            sc[n][2] = sc[n][2]*0.125f + mk.x;
            sc[n][3] = sc[n][3]*0.125f + mk.y;
        }

        // online softmax
        float mx0 = -1e30f, mx1 = -1e30f;
#pragma unroll
        for (int n = 0; n < 8; n++){
            mx0 = fmaxf(mx0, fmaxf(sc[n][0], sc[n][1]));
            mx1 = fmaxf(mx1, fmaxf(sc[n][2], sc[n][3]));
        }
        mx0 = fmaxf(mx0, __shfl_xor_sync(0xffffffffu, mx0, 1));
        mx0 = fmaxf(mx0, __shfl_xor_sync(0xffffffffu, mx0, 2));
        mx1 = fmaxf(mx1, __shfl_xor_sync(0xffffffffu, mx1, 1));
        mx1 = fmaxf(mx1, __shfl_xor_sync(0xffffffffu, mx1, 2));
        float mn0 = fmaxf(m0r, mx0), mn1 = fmaxf(m1r, mx1);
        float al0 = __expf(m0r - mn0), al1 = __expf(m1r - mn1);
        m0r = mn0; m1r = mn1;

        float s0 = 0.f, s1 = 0.f;
        uint32_t ph[8][2], pl[8][2];
#pragma unroll
        for (int n = 0; n < 8; n++){
            float e0 = __expf(sc[n][0] - mn0);
            float e1 = __expf(sc[n][1] - mn0);
            float e2 = __expf(sc[n][2] - mn1);
            float e3 = __expf(sc[n][3] - mn1);
            s0 += e0 + e1;  s1 += e2 + e3;
            __nv_bfloat16 h0 = __float2bfloat16(e0), h1 = __float2bfloat16(e1);
            __nv_bfloat16 h2 = __float2bfloat16(e2), h3 = __float2bfloat16(e3);
            __nv_bfloat162 p0 = __halves2bfloat162(h0, h1);
            __nv_bfloat162 p1 = __halves2bfloat162(h2, h3);
            ph[n][0] = *(uint32_t*)&p0;
            ph[n][1] = *(uint32_t*)&p1;
            pl[n][0] = packbf(e0 - __bfloat162float(h0), e1 - __bfloat162float(h1));
            pl[n][1] = packbf(e2 - __bfloat162float(h2), e3 - __bfloat162float(h3));
        }
        s0 += __shfl_xor_sync(0xffffffffu, s0, 1);
        s0 += __shfl_xor_sync(0xffffffffu, s0, 2);
        s1 += __shfl_xor_sync(0xffffffffu, s1, 1);
        s1 += __shfl_xor_sync(0xffffffffu, s1, 2);
        ls0 = ls0*al0 + s0;
        ls1 = ls1*al1 + s1;
#pragma unroll
        for (int n = 0; n < 8; n++){
            o[n][0] *= al0; o[n][1] *= al0;
            o[n][2] *= al1; o[n][3] *= al1;
        }

        // ---- wait V (KE[i+1] may remain in flight), then PV ----
        if (more) cp_wait<1>(); else cp_wait<0>();
        __syncthreads();

        const int il16 = lane & 15;
        const int gt   = lane >> 4;
#pragma unroll
        for (int kk = 0; kk < 4; kk++){
            uint32_t ah[4] = { ph[2*kk][0], ph[2*kk][1], ph[2*kk+1][0], ph[2*kk+1][1] };
            uint32_t al_[4]= { pl[2*kk][0], pl[2*kk][1], pl[2*kk+1][0], pl[2*kk+1][1] };
#pragma unroll
            for (int n2 = 0; n2 < 4; n2++){
                int row = 16*kk + il16;
                int ch  = 2*n2 + gt;
                uint32_t vh4[4], vl4[4];
                ldsm4t(vh4, sw_addr(sm, F_VHI, row, ch));
                ldsm4t(vl4, sw_addr(sm, F_VLO, row, ch));
                mma_bf16(o[2*n2  ], ah,  vh4[0], vh4[1]);
                mma_bf16(o[2*n2  ], ah,  vl4[0], vl4[1]);
                mma_bf16(o[2*n2  ], al_, vh4[0], vh4[1]);
                mma_bf16(o[2*n2+1], ah,  vh4[2], vh4[3]);
                mma_bf16(o[2*n2+1], ah,  vl4[2], vl4[3]);
                mma_bf16(o[2*n2+1], al_, vh4[2], vh4[3]);
            }
        }
    }

    // epilogue
    const float inv0 = 1.0f / ls0;
    const float inv1 = 1.0f / ls1;
#pragma unroll
    for (int n = 0; n < 8; n++){
        int col = head*64 + 8*n + 2*quad;
        float2 r0v = make_float2(o[n][0]*inv0, o[n][1]*inv0);
        float2 r1v = make_float2(o[n][2]*inv1, o[n][3]*inv1);
        *(float2*)&out[((size_t)b_*L_ + l0 + lw    )*H_ + col] = r0v;
        *(float2*)&out[((size_t)b_*L_ + l0 + lw + 8)*H_ + col] = r1v;
    }
}

// ---------------------------------------------------------------------------
extern "C" void kernel_launch(void* const* d_in, const int* in_sizes, int n_in,
                              void* d_out, int out_size)
{
    const float* hidden   = (const float*)d_in[0];
    const float* mask     = (const float*)d_in[1];
    const float* Wq       = (const float*)d_in[2];
    const float* bq       = (const float*)d_in[3];
    const float* Wk       = (const float*)d_in[4];
    const float* bk       = (const float*)d_in[5];
    const float* Wv       = (const float*)d_in[6];
    const float* bv       = (const float*)d_in[7];
    const float* dist_emb = (const float*)d_in[8];
    float* out            = (float*)d_out;

    cudaFuncSetAttribute(qkv_mma,
        cudaFuncAttributeMaxDynamicSharedMemorySize, QKV_SMEM);
    cudaFuncSetAttribute(flash_kernel,
        cudaFuncAttributeMaxDynamicSharedMemorySize, FLASH_SMEM);

    prep_split<<<(M_*H_)/256, 256>>>(hidden, 0, M_*H_);
    prep_split<<<(H_*H_)/256, 256>>>(Wq, 1, H_*H_);
    prep_split<<<(H_*H_)/256, 256>>>(Wk, 2, H_*H_);
    prep_split<<<(H_*H_)/256, 256>>>(Wv, 3, H_*H_);
    prep_e_kernel<<<(NDIST*HD_ + 255)/256, 256>>>(dist_emb);

    qkv_mma<<<dim3(H_/64, M_/128, 3), 128, QKV_SMEM>>>(bq, bk, bv);
    flash_kernel<<<dim3(L_/64, BH_), 128, FLASH_SMEM>>>(mask, out);
}

// round 12
// speedup vs baseline: 1.2112x; 1.2112x over previous
#include <cuda_runtime.h>
#include <cuda_bf16.h>
#include <math.h>
#include <stdint.h>

#define B_  2
#define L_  2048
#define H_  1024
#define NH_ 16
#define HD_ 64
#define BH_ 32
#define M_  4096
#define MAXPOS_ 2048
#define NDIST 4095

// ---------------- device-global scratch (allocation-free) ----------------
__device__ __nv_bfloat16 g_hhi[(size_t)M_*H_];
__device__ __nv_bfloat16 g_hlo[(size_t)M_*H_];
__device__ __nv_bfloat16 g_whi[3][(size_t)H_*H_];
__device__ __nv_bfloat16 g_wlo[3][(size_t)H_*H_];
__device__ __nv_bfloat16 g_qhi[(size_t)BH_*L_*HD_];
__device__ __nv_bfloat16 g_qlo[(size_t)BH_*L_*HD_];
__device__ __nv_bfloat16 g_khi[(size_t)BH_*L_*HD_];
__device__ __nv_bfloat16 g_klo[(size_t)BH_*L_*HD_];
__device__ __nv_bfloat16 g_vhi[(size_t)BH_*L_*HD_];
__device__ __nv_bfloat16 g_vlo[(size_t)BH_*L_*HD_];
__device__ __nv_bfloat16 g_e[(size_t)NDIST*HD_];

// ---------------- helpers ----------------
__device__ __forceinline__ uint32_t smem_u32(const void* p){
    return (uint32_t)__cvta_generic_to_shared(p);
}
__device__ __forceinline__ void ldsm4(uint32_t* r, uint32_t a){
    asm volatile("ldmatrix.sync.aligned.m8n8.x4.shared.b16 {%0,%1,%2,%3}, [%4];"
        : "=r"(r[0]),"=r"(r[1]),"=r"(r[2]),"=r"(r[3]) : "r"(a));
}
__device__ __forceinline__ void ldsm4t(uint32_t* r, uint32_t a){
    asm volatile("ldmatrix.sync.aligned.m8n8.x4.trans.shared.b16 {%0,%1,%2,%3}, [%4];"
        : "=r"(r[0]),"=r"(r[1]),"=r"(r[2]),"=r"(r[3]) : "r"(a));
}
__device__ __forceinline__ void mma_bf16(float* c, const uint32_t* a, uint32_t b0, uint32_t b1){
    asm volatile(
        "mma.sync.aligned.m16n8k16.row.col.f32.bf16.bf16.f32 "
        "{%0,%1,%2,%3},{%4,%5,%6,%7},{%8,%9},{%0,%1,%2,%3};"
        : "+f"(c[0]), "+f"(c[1]), "+f"(c[2]), "+f"(c[3])
        : "r"(a[0]), "r"(a[1]), "r"(a[2]), "r"(a[3]), "r"(b0), "r"(b1));
}
__device__ __forceinline__ uint32_t packbf(float x, float y){
    __nv_bfloat162 h = __floats2bfloat162_rn(x, y);
    return *reinterpret_cast<uint32_t*>(&h);
}
__device__ __forceinline__ void cp16(uint32_t dst, const void* src){
    asm volatile("cp.async.cg.shared.global [%0], [%1], 16;" :: "r"(dst), "l"(src));
}
__device__ __forceinline__ void cp_commit_wait(){
    asm volatile("cp.async.commit_group;\n cp.async.wait_group 0;" ::: "memory");
}
// tiles have 128B rows (64 bf16); chunk = 16B unit, xor-swizzled
__device__ __forceinline__ uint32_t sw_addr(char* sm, int off, int row, int ch){
    return smem_u32(sm + off + row*128 + (((ch) ^ (row & 7)) << 4));
}

// ---------------- merged prep: fp32 -> bf16 hi/lo planes + e ----------------
// region layout (element offsets in the virtual concatenated input):
//   [0, 4194304)          hidden  -> g_hhi/g_hlo
//   [4194304, 5242880)    Wq      -> g_whi[0]/g_wlo[0]
//   [5242880, 6291456)    Wk      -> g_whi[1]/g_wlo[1]
//   [6291456, 7340032)    Wv      -> g_whi[2]/g_wlo[2]
//   [7340032, 7602112)    dist_emb-> g_e (hi only)
#define N_H   (M_*H_)
#define N_W   (H_*H_)
#define N_E   (NDIST*HD_)
#define N_TOT (N_H + 3*N_W + N_E)

__global__ __launch_bounds__(256) void prep_all(
    const float* __restrict__ hidden, const float* __restrict__ Wq,
    const float* __restrict__ Wk, const float* __restrict__ Wv,
    const float* __restrict__ emb)
{
    int i = blockIdx.x*256 + threadIdx.x;
    if (i >= N_TOT) return;
    if (i >= N_H + 3*N_W){
        int j = i - (N_H + 3*N_W);
        g_e[j] = __float2bfloat16(emb[j]);
        return;
    }
    const float* src;  __nv_bfloat16 *hi, *lo;  int j;
    if (i < N_H){ src = hidden; hi = g_hhi; lo = g_hlo; j = i; }
    else if (i < N_H + N_W){ src = Wq; hi = g_whi[0]; lo = g_wlo[0]; j = i - N_H; }
    else if (i < N_H + 2*N_W){ src = Wk; hi = g_whi[1]; lo = g_wlo[1]; j = i - N_H - N_W; }
    else { src = Wv; hi = g_whi[2]; lo = g_wlo[2]; j = i - N_H - 2*N_W; }
    float x = src[j];
    __nv_bfloat16 h = __float2bfloat16(x);
    hi[j] = h;
    lo[j] = __float2bfloat16(x - __bfloat162float(h));
}

// ---------------- QKV projection via split-bf16 mma ----------------
#define QA_HI 0
#define QA_LO 16384
#define QB_HI 32768
#define QB_LO 40960
#define QKV_SMEM 49152

__global__ __launch_bounds__(128) void qkv_mma(
    const float* __restrict__ bq, const float* __restrict__ bk,
    const float* __restrict__ bv)
{
    extern __shared__ char sm[];
    const int which = blockIdx.z;
    const __nv_bfloat16* Whi = g_whi[which];
    const __nv_bfloat16* Wlo = g_wlo[which];
    const float* bias = (which==0) ? bq : (which==1) ? bk : bv;
    __nv_bfloat16* Ohi = (which==0) ? g_qhi : (which==1) ? g_khi : g_vhi;
    __nv_bfloat16* Olo = (which==0) ? g_qlo : (which==1) ? g_klo : g_vlo;

    const int m0 = blockIdx.y * 128;
    const int n0 = blockIdx.x * 64;
    const int t  = threadIdx.x;
    const int w  = t >> 5;
    const int lane = t & 31;
    const int quad = lane & 3;
    const int g8  = lane >> 3;       // ldsm4 group 0..3
    const int il7 = lane & 7;

    float c[2][8][4];
#pragma unroll
    for (int s = 0; s < 2; s++)
#pragma unroll
        for (int n = 0; n < 8; n++)
#pragma unroll
            for (int j = 0; j < 4; j++) c[s][n][j] = 0.f;

    for (int k0 = 0; k0 < H_; k0 += 64){
        __syncthreads();
#pragma unroll
        for (int rep = 0; rep < 2; rep++){           // A: 2 planes x 128 rows
            int id = t + 128*rep;
            int plane = id >> 7, row = id & 127;
            const char* gs = (const char*)((plane ? g_hlo : g_hhi) + (size_t)(m0+row)*H_ + k0);
            int off = (plane ? QA_LO : QA_HI);
#pragma unroll
            for (int cc = 0; cc < 8; cc++)
                cp16(sw_addr(sm, off, row, cc), gs + cc*16);
        }
        {                                            // B: 2 planes x 64 rows
            int plane = t >> 6, row = t & 63;
            const char* gs = (const char*)((plane ? Wlo : Whi) + (size_t)(n0+row)*H_ + k0);
            int off = (plane ? QB_LO : QB_HI);
#pragma unroll
            for (int cc = 0; cc < 8; cc++)
                cp16(sw_addr(sm, off, row, cc), gs + cc*16);
        }
        cp_commit_wait();
        __syncthreads();

#pragma unroll
        for (int kk = 0; kk < 4; kk++){
            uint32_t ah[2][4], al[2][4];
#pragma unroll
            for (int s = 0; s < 2; s++){
                int row = 32*w + 16*s + (lane & 15);
                int ch  = 2*kk + (lane >> 4);
                ldsm4(ah[s], sw_addr(sm, QA_HI, row, ch));
                ldsm4(al[s], sw_addr(sm, QA_LO, row, ch));
            }
#pragma unroll
            for (int n2 = 0; n2 < 4; n2++){
                int row = 8*(2*n2 + (g8>>1)) + il7;
                int ch  = 2*kk + (g8&1);
                uint32_t bh4[4], bl4[4];
                ldsm4(bh4, sw_addr(sm, QB_HI, row, ch));
                ldsm4(bl4, sw_addr(sm, QB_LO, row, ch));
#pragma unroll
                for (int s = 0; s < 2; s++){
                    mma_bf16(c[s][2*n2  ], ah[s], bh4[0], bh4[1]);
                    mma_bf16(c[s][2*n2  ], ah[s], bl4[0], bl4[1]);
                    mma_bf16(c[s][2*n2  ], al[s], bh4[0], bh4[1]);
                    mma_bf16(c[s][2*n2+1], ah[s], bh4[2], bh4[3]);
                    mma_bf16(c[s][2*n2+1], ah[s], bl4[2], bl4[3]);
                    mma_bf16(c[s][2*n2+1], al[s], bh4[2], bh4[3]);
                }
            }
        }
    }

    const int h = n0 >> 6;
#pragma unroll
    for (int s = 0; s < 2; s++){
#pragma unroll
        for (int n = 0; n < 8; n++){
            int col = 8*n + 2*quad;
            float b0f = bias[n0+col], b1f = bias[n0+col+1];
#pragma unroll
            for (int half = 0; half < 2; half++){
                int mr = m0 + 32*w + 16*s + (lane>>2) + half*8;
                float f0 = c[s][n][half*2+0] + b0f;
                float f1 = c[s][n][half*2+1] + b1f;
                int b_ = mr >> 11, l = mr & (L_-1);
                size_t idx = (((size_t)(b_*NH_ + h))*L_ + l)*HD_ + col;
                __nv_bfloat16 h0 = __float2bfloat16(f0);
                __nv_bfloat16 h1 = __float2bfloat16(f1);
                __nv_bfloat162 hp = __halves2bfloat162(h0, h1);
                __nv_bfloat162 lp = __halves2bfloat162(
                    __float2bfloat16(f0 - __bfloat162float(h0)),
                    __float2bfloat16(f1 - __bfloat162float(h1)));
                *(uint32_t*)&Ohi[idx] = *(uint32_t*)&hp;
                *(uint32_t*)&Olo[idx] = *(uint32_t*)&lp;
            }
        }
    }
}

// ---------------- fused flash attention via mma (R6 best config) ----------
#define OQ_HI 0
#define OQ_LO 8192
#define OK_HI 16384
#define OK_LO 24576
#define OV_HI 32768
#define OV_LO 40960
#define OE    49152
#define O_QE  65536
#define O_KE  82944
#define O_MSK 100352
#define FLASH_SMEM 108544

__global__ __launch_bounds__(128) void flash_kernel(
    const float* __restrict__ mask, float* __restrict__ out)
{
    extern __shared__ char sm[];
    const int bh = blockIdx.y;
    const int l0 = blockIdx.x * 64;
    const int t  = threadIdx.x;
    const int w  = t >> 5;
    const int lane = t & 31;
    const int quad = lane & 3;
    const int g8  = lane >> 3;
    const int il7 = lane & 7;
    const int lw = 16*w + (lane >> 2);
    const size_t gb = (size_t)bh * L_ * HD_;
    const int b_ = bh >> 4, head = bh & 15;

    // stage mask row (2048 floats) + Q hi/lo
    {
        const char* mp = (const char*)(mask + (size_t)b_ * L_);
#pragma unroll
        for (int i = 0; i < 4; i++)
            cp16(smem_u32(sm + O_MSK + (t + 128*i)*16), mp + (t + 128*i)*16);
        int plane = t >> 6, row = t & 63;
        const char* gs = (const char*)((plane ? g_qlo : g_qhi) + gb + (size_t)(l0+row)*HD_);
        int off = (plane ? OQ_LO : OQ_HI);
#pragma unroll
        for (int cc = 0; cc < 8; cc++)
            cp16(sw_addr(sm, off, row, cc), gs + cc*16);
    }
    cp_commit_wait();
    __syncthreads();

    // persistent Q A-fragments
    uint32_t qh[4][4], ql[4][4];
#pragma unroll
    for (int kk = 0; kk < 4; kk++){
        int row = 16*w + (lane & 15);
        int ch  = 2*kk + (lane >> 4);
        ldsm4(qh[kk], sw_addr(sm, OQ_HI, row, ch));
        ldsm4(ql[kk], sw_addr(sm, OQ_LO, row, ch));
    }

    float o[8][4];
#pragma unroll
    for (int n = 0; n < 8; n++)
#pragma unroll
        for (int j = 0; j < 4; j++) o[n][j] = 0.f;
    float m0r = -1e30f, m1r = -1e30f, ls0 = 0.f, ls1 = 0.f;

    for (int r0 = 0; r0 < L_; r0 += 64){
        __syncthreads();
        // stage K,V hi/lo (4 tiles x 64 rows) via cp.async
#pragma unroll
        for (int rep = 0; rep < 2; rep++){
            int id = t + 128*rep;
            int tile = id >> 6, row = id & 63;
            const char* g =
                (const char*)((tile==0 ? g_khi : tile==1 ? g_klo : tile==2 ? g_vhi : g_vlo)
                + gb + (size_t)(r0+row)*HD_);
            int off = (tile==0 ? OK_HI : tile==1 ? OK_LO : tile==2 ? OV_HI : OV_LO);
#pragma unroll
            for (int cc = 0; cc < 8; cc++)
                cp16(sw_addr(sm, off, row, cc), g + cc*16);
        }
        // stage E slab (rows 0..126; row 127 zeroed)
        {
            int gbase = l0 - r0 + (MAXPOS_ - 1) - 63;
            if (t < 127){
                const char* gs = (const char*)(g_e + (size_t)(gbase + t)*HD_);
#pragma unroll
                for (int cc = 0; cc < 8; cc++)
                    cp16(sw_addr(sm, OE, t, cc), gs + cc*16);
            } else if (t == 127){
                uint4 z = make_uint4(0,0,0,0);
                char* d = sm + OE + 127*128;
#pragma unroll
                for (int cc = 0; cc < 8; cc++)
                    *(uint4*)(d + ((cc ^ 7) << 4)) = z;
            }
        }
        cp_commit_wait();
        __syncthreads();

        // ---- QE/KE bias GEMMs, band-trimmed to 10 n-tiles each ----
        {
            uint32_t ka[4][4];
#pragma unroll
            for (int kk = 0; kk < 4; kk++){
                int row = 16*w + (lane & 15);
                int ch  = 2*kk + (lane >> 4);
                ldsm4(ka[kk], sw_addr(sm, OK_HI, row, ch));
            }
            __nv_bfloat16* qe = (__nv_bfloat16*)(sm + O_QE);
            __nv_bfloat16* ke = (__nv_bfloat16*)(sm + O_KE);
            const int nq0 = 2*w;       // QE band: d-tiles 2w .. 2w+9
            const int nk0 = 6 - 2*w;   // KE band: d-tiles 6-2w .. 15-2w
#pragma unroll
            for (int p = 0; p < 5; p++){
                float cq[2][4] = {{0.f,0.f,0.f,0.f},{0.f,0.f,0.f,0.f}};
                float ck[2][4] = {{0.f,0.f,0.f,0.f},{0.f,0.f,0.f,0.f}};
#pragma unroll
                for (int kk = 0; kk < 4; kk++){
                    int ch = 2*kk + (g8&1);
                    uint32_t eq[4], ek[4];
                    ldsm4(eq, sw_addr(sm, OE, 8*(nq0 + 2*p + (g8>>1)) + il7, ch));
                    ldsm4(ek, sw_addr(sm, OE, 8*(nk0 + 2*p + (g8>>1)) + il7, ch));
                    mma_bf16(cq[0], qh[kk], eq[0], eq[1]);
                    mma_bf16(cq[1], qh[kk], eq[2], eq[3]);
                    mma_bf16(ck[0], ka[kk], ek[0], ek[1]);
                    mma_bf16(ck[1], ka[kk], ek[2], ek[3]);
                }
#pragma unroll
                for (int u = 0; u < 2; u++){
                    int cq_col = 8*(nq0 + 2*p + u) + 2*quad;
                    int ck_col = 8*(nk0 + 2*p + u) + 2*quad;
                    *(uint32_t*)&qe[(size_t)lw*136 + cq_col]     = packbf(cq[u][0], cq[u][1]);
                    *(uint32_t*)&qe[(size_t)(lw+8)*136 + cq_col] = packbf(cq[u][2], cq[u][3]);
                    *(uint32_t*)&ke[(size_t)lw*136 + ck_col]     = packbf(ck[u][0], ck[u][1]);
                    *(uint32_t*)&ke[(size_t)(lw+8)*136 + ck_col] = packbf(ck[u][2], ck[u][3]);
                }
            }
        }
        __syncthreads();

        // ---- S1 = Q@K^T (3-mma split), C init from diagonal gathers ----
        float sc[8][4];
        const __nv_bfloat16* qe = (const __nv_bfloat16*)(sm + O_QE);
        const __nv_bfloat16* ke = (const __nv_bfloat16*)(sm + O_KE);
#pragma unroll
        for (int n = 0; n < 8; n++){
            int r  = 8*n + 2*quad;
            int d0 = lw - r + 63;
            sc[n][0] = __bfloat162float(qe[(size_t)lw*136 + d0])
                     + __bfloat162float(ke[(size_t)r*136 + d0]);
            sc[n][1] = __bfloat162float(qe[(size_t)lw*136 + d0 - 1])
                     + __bfloat162float(ke[(size_t)(r+1)*136 + d0 - 1]);
            sc[n][2] = __bfloat162float(qe[(size_t)(lw+8)*136 + d0 + 8])
                     + __bfloat162float(ke[(size_t)r*136 + d0 + 8]);
            sc[n][3] = __bfloat162float(qe[(size_t)(lw+8)*136 + d0 + 7])
                     + __bfloat162float(ke[(size_t)(r+1)*136 + d0 + 7]);
        }
#pragma unroll
        for (int n2 = 0; n2 < 4; n2++){
#pragma unroll
            for (int kk = 0; kk < 4; kk++){
                int row = 8*(2*n2 + (g8>>1)) + il7;
                int ch  = 2*kk + (g8&1);
                uint32_t kh4[4], kl4[4];
                ldsm4(kh4, sw_addr(sm, OK_HI, row, ch));
                ldsm4(kl4, sw_addr(sm, OK_LO, row, ch));
                mma_bf16(sc[2*n2  ], qh[kk], kh4[0], kh4[1]);
                mma_bf16(sc[2*n2  ], qh[kk], kl4[0], kl4[1]);
                mma_bf16(sc[2*n2  ], ql[kk], kh4[0], kh4[1]);
                mma_bf16(sc[2*n2+1], qh[kk], kh4[2], kh4[3]);
                mma_bf16(sc[2*n2+1], qh[kk], kl4[2], kl4[3]);
                mma_bf16(sc[2*n2+1], ql[kk], kh4[2], kh4[3]);
            }
        }

        // logits = sc*0.125 + mask
        const float* msf = (const float*)(sm + O_MSK);
#pragma unroll
        for (int n = 0; n < 8; n++){
            float2 mk = *(const float2*)&msf[r0 + 8*n + 2*quad];
            sc[n][0] = sc[n][0]*0.125f + mk.x;
            sc[n][1] = sc[n][1]*0.125f + mk.y;
            sc[n][2] = sc[n][2]*0.125f + mk.x;
            sc[n][3] = sc[n][3]*0.125f + mk.y;
        }

        // online softmax (rows lw, lw+8); quad shfl reduce
        float mx0 = -1e30f, mx1 = -1e30f;
#pragma unroll
        for (int n = 0; n < 8; n++){
            mx0 = fmaxf(mx0, fmaxf(sc[n][0], sc[n][1]));
            mx1 = fmaxf(mx1, fmaxf(sc[n][2], sc[n][3]));
        }
        mx0 = fmaxf(mx0, __shfl_xor_sync(0xffffffffu, mx0, 1));
        mx0 = fmaxf(mx0, __shfl_xor_sync(0xffffffffu, mx0, 2));
        mx1 = fmaxf(mx1, __shfl_xor_sync(0xffffffffu, mx1, 1));
        mx1 = fmaxf(mx1, __shfl_xor_sync(0xffffffffu, mx1, 2));
        float mn0 = fmaxf(m0r, mx0), mn1 = fmaxf(m1r, mx1);
        float al0 = __expf(m0r - mn0), al1 = __expf(m1r - mn1);
        m0r = mn0; m1r = mn1;

        float s0 = 0.f, s1 = 0.f;
        uint32_t ph[8][2], pl[8][2];
#pragma unroll
        for (int n = 0; n < 8; n++){
            float e0 = __expf(sc[n][0] - mn0);
            float e1 = __expf(sc[n][1] - mn0);
            float e2 = __expf(sc[n][2] - mn1);
            float e3 = __expf(sc[n][3] - mn1);
            s0 += e0 + e1;  s1 += e2 + e3;
            __nv_bfloat16 h0 = __float2bfloat16(e0), h1 = __float2bfloat16(e1);
            __nv_bfloat16 h2 = __float2bfloat16(e2), h3 = __float2bfloat16(e3);
            __nv_bfloat162 p0 = __halves2bfloat162(h0, h1);
            __nv_bfloat162 p1 = __halves2bfloat162(h2, h3);
            ph[n][0] = *(uint32_t*)&p0;
            ph[n][1] = *(uint32_t*)&p1;
            pl[n][0] = packbf(e0 - __bfloat162float(h0), e1 - __bfloat162float(h1));
            pl[n][1] = packbf(e2 - __bfloat162float(h2), e3 - __bfloat162float(h3));
        }
        s0 += __shfl_xor_sync(0xffffffffu, s0, 1);
        s0 += __shfl_xor_sync(0xffffffffu, s0, 2);
        s1 += __shfl_xor_sync(0xffffffffu, s1, 1);
        s1 += __shfl_xor_sync(0xffffffffu, s1, 2);
        ls0 = ls0*al0 + s0;
        ls1 = ls1*al1 + s1;
#pragma unroll
        for (int n = 0; n < 8; n++){
            o[n][0] *= al0; o[n][1] *= al0;
            o[n][2] *= al1; o[n][3] *= al1;
        }

        // ---- PV: O += P @ V (reg A-frags, paired ldsm4t V B-frags) ----
        const int il16 = lane & 15;
        const int gt   = lane >> 4;
#pragma unroll
        for (int kk = 0; kk < 4; kk++){
            uint32_t ah[4] = { ph[2*kk][0], ph[2*kk][1], ph[2*kk+1][0], ph[2*kk+1][1] };
            uint32_t al_[4]= { pl[2*kk][0], pl[2*kk][1], pl[2*kk+1][0], pl[2*kk+1][1] };
#pragma unroll
            for (int n2 = 0; n2 < 4; n2++){
                int row = 16*kk + il16;
                int ch  = 2*n2 + gt;
                uint32_t vh4[4], vl4[4];
                ldsm4t(vh4, sw_addr(sm, OV_HI, row, ch));
                ldsm4t(vl4, sw_addr(sm, OV_LO, row, ch));
                mma_bf16(o[2*n2  ], ah,  vh4[0], vh4[1]);
                mma_bf16(o[2*n2  ], ah,  vl4[0], vl4[1]);
                mma_bf16(o[2*n2  ], al_, vh4[0], vh4[1]);
                mma_bf16(o[2*n2+1], ah,  vh4[2], vh4[3]);
                mma_bf16(o[2*n2+1], ah,  vl4[2], vl4[3]);
                mma_bf16(o[2*n2+1], al_, vh4[2], vh4[3]);
            }
        }
    }

    // epilogue
    const float inv0 = 1.0f / ls0;
    const float inv1 = 1.0f / ls1;
#pragma unroll
    for (int n = 0; n < 8; n++){
        int col = head*64 + 8*n + 2*quad;
        float2 r0v = make_float2(o[n][0]*inv0, o[n][1]*inv0);
        float2 r1v = make_float2(o[n][2]*inv1, o[n][3]*inv1);
        *(float2*)&out[((size_t)b_*L_ + l0 + lw    )*H_ + col] = r0v;
        *(float2*)&out[((size_t)b_*L_ + l0 + lw + 8)*H_ + col] = r1v;
    }
}

// ---------------------------------------------------------------------------
extern "C" void kernel_launch(void* const* d_in, const int* in_sizes, int n_in,
                              void* d_out, int out_size)
{
    const float* hidden   = (const float*)d_in[0];
    const float* mask     = (const float*)d_in[1];
    const float* Wq       = (const float*)d_in[2];
    const float* bq       = (const float*)d_in[3];
    const float* Wk       = (const float*)d_in[4];
    const float* bk       = (const float*)d_in[5];
    const float* Wv       = (const float*)d_in[6];
    const float* bv       = (const float*)d_in[7];
    const float* dist_emb = (const float*)d_in[8];
    float* out            = (float*)d_out;

    cudaFuncSetAttribute(qkv_mma,
        cudaFuncAttributeMaxDynamicSharedMemorySize, QKV_SMEM);
    cudaFuncSetAttribute(flash_kernel,
        cudaFuncAttributeMaxDynamicSharedMemorySize, FLASH_SMEM);

    // ONE prep launch (also places flash at skip-5 for the ncu capture)
    prep_all<<<(N_TOT + 255)/256, 256>>>(hidden, Wq, Wk, Wv, dist_emb);

    qkv_mma<<<dim3(H_/64, M_/128, 3), 128, QKV_SMEM>>>(bq, bk, bv);
    flash_kernel<<<dim3(L_/64, BH_), 128, FLASH_SMEM>>>(mask, out);
}